// round 3
// baseline (speedup 1.0000x reference)
#include <cuda_runtime.h>
#include <math.h>

// ANI AEV computer. M=32, A=48, S=4.
// Radial: 4 species x 16 ShfR = 64 ch. Angular: 10 sp-pairs x 4 ShfA x 8 ShfZ = 320 ch.
// Output (32, 48, 384) fp32.
//
// R1: lane-staggered shared atomics.
// R2: 4 threads per angular pair (thread=(pair,ia)), closed-form pair decode,
//     per-neighbor fc/species precompute, register-cached cosZ/sinZ.

#define MM 32
#define AA 48
#define SS 4
#define NSHFR 16
#define NSHFA 4
#define NSHFZ 8
#define RAD_SUB 16
#define ANG_SUB 32
#define NPAIRS_SP 10
#define OUT_PER_ATOM (SS * RAD_SUB + NPAIRS_SP * ANG_SUB)  // 384
#define RCR_F 5.2f
#define RCA_F 3.5f
#define NTHREADS 128

__global__ __launch_bounds__(NTHREADS)
void aev_kernel(const float* __restrict__ coords,
                const float* __restrict__ EtaR,
                const float* __restrict__ ShfR,
                const float* __restrict__ EtaA,
                const float* __restrict__ Zeta,
                const float* __restrict__ ShfA,
                const float* __restrict__ ShfZ,
                const int*   __restrict__ species,
                float*       __restrict__ out)
{
    const int m    = blockIdx.x / AA;
    const int ci   = blockIdx.x % AA;
    const int tid  = threadIdx.x;
    const int lane = tid & 31;

    __shared__ float sx[AA], sy[AA], sz[AA];
    __shared__ int   ssp[AA];
    __shared__ float acc[OUT_PER_ATOM];
    __shared__ float shfR[NSHFR], shfA[NSHFA];
    __shared__ float cz2[NSHFZ], sz2[NSHFZ];    // 0.5*cos(ShfZ), 0.5*sin(ShfZ)
    __shared__ int   ptab[SS * SS];             // species-pair -> triu index
    __shared__ float s_etaR, s_etaA, s_zeta;
    __shared__ int   nnb;
    __shared__ float nbd[AA], nbx[AA], nby[AA], nbz[AA], nbfc[AA];
    __shared__ int   nbsp[AA];

    if (tid < AA) {
        sx[tid]  = coords[(m * AA + tid) * 3 + 0];
        sy[tid]  = coords[(m * AA + tid) * 3 + 1];
        sz[tid]  = coords[(m * AA + tid) * 3 + 2];
        ssp[tid] = species[m * AA + tid];
    }
    if (tid < NSHFR) shfR[tid] = ShfR[tid];
    if (tid < NSHFA) shfA[tid] = ShfA[tid];
    if (tid < NSHFZ) {
        float s = ShfZ[tid];
        cz2[tid] = 0.5f * cosf(s);
        sz2[tid] = 0.5f * sinf(s);
    }
    if (tid < SS * SS) {
        int r = tid / SS, c = tid % SS;
        int lo = min(r, c), hi = max(r, c);
        ptab[tid] = lo * SS - (lo * (lo - 1)) / 2 + (hi - lo);
    }
    if (tid == 0) {
        s_etaR = EtaR[0];
        s_etaA = EtaA[0];
        s_zeta = Zeta[0];
        nnb = 0;
    }
    for (int c = tid; c < OUT_PER_ATOM; c += NTHREADS) acc[c] = 0.0f;
    __syncthreads();

    const float cxi = sx[ci], cyi = sy[ci], czi = sz[ci];

    // ---- radial contributions + angular neighbor list build ----
    if (tid < AA && tid != ci) {
        const int j = tid;
        const float dx = sx[j] - cxi;
        const float dy = sy[j] - cyi;
        const float dz = sz[j] - czi;
        const float d  = sqrtf(dx * dx + dy * dy + dz * dz);

        if (d <= RCR_F) {
            const float fc   = 0.5f * __cosf(d * (float)(M_PI / 5.2)) + 0.5f;
            const float base = 0.25f * fc;
            const int   off  = ssp[j] * RAD_SUB;
            const float eR   = s_etaR;
            #pragma unroll
            for (int k = 0; k < NSHFR; k++) {
                const int t = (k + lane) & (NSHFR - 1);
                const float x = d - shfR[t];
                atomicAdd(&acc[off + t], base * __expf(-eR * x * x));
            }
        }
        if (d <= RCA_F) {
            const int slot = atomicAdd(&nnb, 1);
            nbd[slot]  = d;
            nbx[slot]  = dx;
            nby[slot]  = dy;
            nbz[slot]  = dz;
            nbfc[slot] = 0.5f * __cosf(d * (float)(M_PI / 3.5)) + 0.5f;
            nbsp[slot] = ssp[j];
        }
    }
    __syncthreads();

    // cache angle-shift constants in registers
    float rcz[NSHFZ], rsz[NSHFZ];
    #pragma unroll
    for (int i = 0; i < NSHFZ; i++) { rcz[i] = cz2[i]; rsz[i] = sz2[i]; }
    float rshfA[NSHFA];
    #pragma unroll
    for (int i = 0; i < NSHFA; i++) rshfA[i] = shfA[i];

    // ---- angular: one work item per (pair, ia). 4 items per pair. ----
    const int n      = nnb;
    const int npair  = n * (n - 1) / 2;
    const int nitems = npair * NSHFA;
    const float etaA = s_etaA;
    const float zeta = s_zeta;
    const bool  z32  = (zeta == 32.0f);
    const int   twon1 = 2 * n - 1;
    const int   stag  = (lane >> 2) & 7;   // distinct among lanes sharing ia

    for (int idx = tid; idx < nitems; idx += NTHREADS) {
        const int p  = idx >> 2;
        const int ia = idx & 3;

        // closed-form decode p -> (a, b), a < b
        // row a starts at S(a) = a*(2n-a-1)/2; a = floor(((2n-1)-sqrt((2n-1)^2-8p))/2)
        const float disc = (float)(twon1 * twon1 - 8 * p);
        int a = (int)floorf(((float)twon1 - sqrtf(disc)) * 0.5f);
        int Sa = (a * (2 * n - a - 1)) >> 1;
        if (Sa > p)      { a--; Sa = (a * (2 * n - a - 1)) >> 1; }
        else { const int Sn = ((a + 1) * (2 * n - a - 2)) >> 1;
               if (Sn <= p) { a++; Sa = Sn; } }
        const int b = a + 1 + (p - Sa);

        const float d1 = nbd[a], d2 = nbd[b];
        const float inv = __fdividef(1.0f, fmaxf(d1, 1e-8f) * fmaxf(d2, 1e-8f));
        const float dot = nbx[a] * nbx[b] + nby[a] * nby[b] + nbz[a] * nbz[b];
        const float c   = 0.95f * dot * inv;
        const float sn  = sqrtf(fmaxf(1.0f - c * c, 0.0f));

        const float fcj2 = 2.0f * nbfc[a] * nbfc[b];
        const float dm   = 0.5f * (d1 + d2);
        const int  pidx  = ptab[nbsp[a] * SS + nbsp[b]];

        const float x  = dm - rshfA[ia];
        const float f2 = __expf(-etaA * x * x) * fcj2;

        float* dst = &acc[SS * RAD_SUB + pidx * ANG_SUB + ia * NSHFZ];

        #pragma unroll
        for (int jz = 0; jz < NSHFZ; jz++) {
            const int iz = (jz + stag) & (NSHFZ - 1);
            // cos(arccos(c) - ShfZ) = c*cosZ + sqrt(1-c^2)*sinZ
            const float cz = fmaf(c, rcz[iz], fmaf(sn, rsz[iz], 0.5f));
            float f1;
            if (z32) {
                float t = cz * cz;  // ^2
                t *= t;             // ^4
                t *= t;             // ^8
                t *= t;             // ^16
                t *= t;             // ^32
                f1 = t;
            } else {
                f1 = __powf(cz, zeta);
            }
            atomicAdd(&dst[iz], f1 * f2);
        }
    }
    __syncthreads();

    // ---- write out ----
    float* o = out + (size_t)(m * AA + ci) * OUT_PER_ATOM;
    for (int c = tid; c < OUT_PER_ATOM; c += NTHREADS) o[c] = acc[c];
}

extern "C" void kernel_launch(void* const* d_in, const int* in_sizes, int n_in,
                              void* d_out, int out_size)
{
    const float* coords  = (const float*)d_in[0];
    const float* EtaR    = (const float*)d_in[1];
    const float* ShfR    = (const float*)d_in[2];
    const float* EtaA    = (const float*)d_in[3];
    const float* Zeta    = (const float*)d_in[4];
    const float* ShfA    = (const float*)d_in[5];
    const float* ShfZ    = (const float*)d_in[6];
    const int*   species = (const int*)d_in[7];
    float* out = (float*)d_out;

    aev_kernel<<<MM * AA, NTHREADS>>>(coords, EtaR, ShfR, EtaA, Zeta,
                                      ShfA, ShfZ, species, out);
}